// round 9
// baseline (speedup 1.0000x reference)
#include <cuda_runtime.h>
#include <cuda_bf16.h>
#include <cuda_fp16.h>
#include <cstdint>

#define NN_MAX 50000
#define NE_MAX 800000
#define HID 128

// ---------------- scratch (device globals) ----------------
__device__ int    g_deg[NN_MAX];
__device__ int    g_off[NN_MAX + 1];
__device__ int    g_cursor[NN_MAX];
__device__ int    g_adj[NE_MAX];
__device__ float  g_dinv[NN_MAX];
__device__ __half g_ht[NN_MAX * HID];
__device__ float  g_act[NN_MAX * HID];
__device__ int    g_base[1];
// W hi/lo bf16, [K][N] row-major
__device__ unsigned short g_Whi1[HID * HID];
__device__ unsigned short g_Wlo1[HID * HID];
__device__ unsigned short g_Whi2[HID * HID];
__device__ unsigned short g_Wlo2[HID * HID];

// side stream + events (created at load; no device memory)
static cudaStream_t g_s2 = nullptr;
static cudaEvent_t  g_ev0 = nullptr, g_ev1 = nullptr;
namespace {
struct SideInit {
    SideInit() {
        cudaStreamCreateWithFlags(&g_s2, cudaStreamNonBlocking);
        cudaEventCreateWithFlags(&g_ev0, cudaEventDisableTiming);
        cudaEventCreateWithFlags(&g_ev1, cudaEventDisableTiming);
    }
};
SideInit g_side_init;
}

// ---------------- CSR build ----------------
__global__ void k_count(const int* __restrict__ dst, int* deg, int E) {
    int e = blockIdx.x * blockDim.x + threadIdx.x;
    if (e < E) atomicAdd(&deg[dst[e]], 1);
}

// fused: block-local exclusive scan + atomic block base.
// NOTE: off[] is an ORDER-FREE partition (not monotonic across blocks);
// the end of node i's range is off[i] + deg[i], NEVER off[i+1].
__global__ void k_assign(const int* __restrict__ deg, int* off, int* cursor,
                         float* dinv, int* base, int n) {
    __shared__ int s[256];
    __shared__ int blk_base;
    int tid = threadIdx.x;
    int gid = blockIdx.x * 256 + tid;
    int v = (gid < n) ? deg[gid] : 0;
    s[tid] = v;
    __syncthreads();
    #pragma unroll
    for (int d = 1; d < 256; d <<= 1) {
        int t = (tid >= d) ? s[tid - d] : 0;
        __syncthreads();
        s[tid] += t;
        __syncthreads();
    }
    if (tid == 255) blk_base = atomicAdd(base, s[255]);
    __syncthreads();
    if (gid < n) {
        int o = blk_base + s[tid] - v;
        off[gid] = o;
        cursor[gid] = o;
        dinv[gid] = rsqrtf((float)(v + 1));
    }
}

__global__ void k_fill_adj(const int* __restrict__ src, const int* __restrict__ dst,
                           int* cursor, int* adj, int E) {
    int e = blockIdx.x * blockDim.x + threadIdx.x;
    if (e < E) {
        int d = dst[e];
        int pos = atomicAdd(&cursor[d], 1);
        adj[pos] = src[e];
    }
}

// ---------------- W prep (both layers, one launch) ----------------
__global__ void k_prepW2(const float* __restrict__ Wa, unsigned short* hia, unsigned short* loa,
                         const float* __restrict__ Wb, unsigned short* hib, unsigned short* lob) {
    int e = blockIdx.x * 256 + threadIdx.x;
    const float* W = (e < HID * HID) ? Wa : Wb;
    unsigned short* hi = (e < HID * HID) ? hia : hib;
    unsigned short* lo = (e < HID * HID) ? loa : lob;
    int idx = (e < HID * HID) ? e : e - HID * HID;
    float w = W[idx];
    __nv_bfloat16 h = __float2bfloat16(w);
    float r = w - __bfloat162float(h);
    __nv_bfloat16 l = __float2bfloat16(r);
    hi[idx] = __bfloat16_as_ushort(h);
    lo[idx] = __bfloat16_as_ushort(l);
}

// ---------------- HMMA GEMM: ht[i,:] = fp16( (X[i,:] @ W) * dinv[i] ) ----------------
#define LDA 136
#define TILE_B (128 * LDA * 2)
#define GEMM_SMEM (4 * TILE_B)

__device__ __forceinline__ uint32_t smem_u32(const void* p) {
    uint32_t a;
    asm("{ .reg .u64 t; cvta.to.shared.u64 t, %1; cvt.u32.u64 %0, t; }" : "=r"(a) : "l"(p));
    return a;
}
__device__ __forceinline__ void ldsm_x4(uint32_t* r, uint32_t addr) {
    asm volatile("ldmatrix.sync.aligned.m8n8.x4.shared.b16 {%0,%1,%2,%3}, [%4];"
                 : "=r"(r[0]), "=r"(r[1]), "=r"(r[2]), "=r"(r[3]) : "r"(addr));
}
__device__ __forceinline__ void ldsm_x2t(uint32_t* r, uint32_t addr) {
    asm volatile("ldmatrix.sync.aligned.m8n8.x2.trans.shared.b16 {%0,%1}, [%2];"
                 : "=r"(r[0]), "=r"(r[1]) : "r"(addr));
}
__device__ __forceinline__ void mma_bf16(float* c, const uint32_t* a, const uint32_t* b) {
    asm volatile("mma.sync.aligned.m16n8k16.row.col.f32.bf16.bf16.f32 "
                 "{%0,%1,%2,%3}, {%4,%5,%6,%7}, {%8,%9}, {%0,%1,%2,%3};"
                 : "+f"(c[0]), "+f"(c[1]), "+f"(c[2]), "+f"(c[3])
                 : "r"(a[0]), "r"(a[1]), "r"(a[2]), "r"(a[3]), "r"(b[0]), "r"(b[1]));
}

__global__ __launch_bounds__(256, 1)
void k_gemm_mma(const float* __restrict__ X,
                const unsigned short* __restrict__ Whi,
                const unsigned short* __restrict__ Wlo,
                const float* __restrict__ dinv,
                __half* __restrict__ out, int n)
{
    extern __shared__ char sm[];
    char* pAhi = sm;
    char* pAlo = sm + TILE_B;
    char* pBhi = sm + 2 * TILE_B;
    char* pBlo = sm + 3 * TILE_B;
    uint32_t uAhi = smem_u32(pAhi), uAlo = smem_u32(pAlo);
    uint32_t uBhi = smem_u32(pBhi), uBlo = smem_u32(pBlo);

    int tid = threadIdx.x, wid = tid >> 5, lid = tid & 31;
    int row0 = blockIdx.x * 128;

    // copy W hi/lo into smem (padded rows)
    {
        const uint4* sh = (const uint4*)Whi;
        const uint4* sl = (const uint4*)Wlo;
        uint4* dh = (uint4*)pBhi;
        uint4* dl = (uint4*)pBlo;
        #pragma unroll
        for (int i = 0; i < 8; ++i) {
            int idx = i * 256 + tid;
            int k = idx >> 4, g = idx & 15;
            dh[k * 17 + g] = sh[idx];
            dl[k * 17 + g] = sl[idx];
        }
    }

    // convert X tile fp32 -> bf16 hi/lo
    {
        const float4* Xg = (const float4*)X;
        #pragma unroll
        for (int i = 0; i < 8; ++i) {
            int idx = i * 256 + tid;
            int r = idx >> 4, g = idx & 15;
            int grow = row0 + r;
            float4 v0 = make_float4(0.f, 0.f, 0.f, 0.f);
            float4 v1 = make_float4(0.f, 0.f, 0.f, 0.f);
            if (grow < n) {
                v0 = __ldg(&Xg[grow * 32 + g * 2]);
                v1 = __ldg(&Xg[grow * 32 + g * 2 + 1]);
            }
            float f[8] = {v0.x, v0.y, v0.z, v0.w, v1.x, v1.y, v1.z, v1.w};
            uint32_t ph[4], pl[4];
            #pragma unroll
            for (int q = 0; q < 4; ++q) {
                __nv_bfloat16 h0 = __float2bfloat16(f[q * 2]);
                __nv_bfloat16 h1 = __float2bfloat16(f[q * 2 + 1]);
                float r0 = f[q * 2]     - __bfloat162float(h0);
                float r1 = f[q * 2 + 1] - __bfloat162float(h1);
                __nv_bfloat16 l0 = __float2bfloat16(r0);
                __nv_bfloat16 l1 = __float2bfloat16(r1);
                ph[q] = ((uint32_t)__bfloat16_as_ushort(h1) << 16) | __bfloat16_as_ushort(h0);
                pl[q] = ((uint32_t)__bfloat16_as_ushort(l1) << 16) | __bfloat16_as_ushort(l0);
            }
            uint4* dh = (uint4*)pAhi;
            uint4* dl = (uint4*)pAlo;
            dh[r * 17 + g] = make_uint4(ph[0], ph[1], ph[2], ph[3]);
            dl[r * 17 + g] = make_uint4(pl[0], pl[1], pl[2], pl[3]);
        }
    }
    __syncthreads();

    // mainloop (R6-proven B-fragment path)
    int m0 = wid * 16;
    float c[16][4];
    #pragma unroll
    for (int t = 0; t < 16; ++t)
        #pragma unroll
        for (int q = 0; q < 4; ++q) c[t][q] = 0.f;

    int a_row = m0 + (lid & 15);
    int a_k8  = (lid >> 4) * 8;
    int b_row = (lid & 15);

    #pragma unroll
    for (int ks = 0; ks < 8; ++ks) {
        int kb = ks * 16;
        uint32_t ahi[4], alo[4];
        uint32_t a_off = ((uint32_t)(a_row * LDA + kb + a_k8)) * 2u;
        ldsm_x4(ahi, uAhi + a_off);
        ldsm_x4(alo, uAlo + a_off);

        uint32_t b_base = ((uint32_t)((kb + b_row) * LDA)) * 2u;
        #pragma unroll
        for (int nt = 0; nt < 16; ++nt) {
            uint32_t bhi[2], blo[2];
            uint32_t b_off = b_base + nt * 16u;
            ldsm_x2t(bhi, uBhi + b_off);
            ldsm_x2t(blo, uBlo + b_off);
            mma_bf16(c[nt], ahi, bhi);
            mma_bf16(c[nt], ahi, blo);
            mma_bf16(c[nt], alo, bhi);
        }
    }

    // epilogue: scale by dinv, store fp16
    {
        int ml = lid >> 2;
        int n0 = (lid & 3) * 2;
        int r0g = row0 + m0 + ml;
        int r1g = r0g + 8;
        float s0 = (r0g < n) ? dinv[r0g] : 0.f;
        float s1 = (r1g < n) ? dinv[r1g] : 0.f;
        #pragma unroll
        for (int nt = 0; nt < 16; ++nt) {
            int col = nt * 8 + n0;
            if (r0g < n) {
                __half2 h = __floats2half2_rn(c[nt][0] * s0, c[nt][1] * s0);
                *(__half2*)(out + (size_t)r0g * HID + col) = h;
            }
            if (r1g < n) {
                __half2 h = __floats2half2_rn(c[nt][2] * s1, c[nt][3] * s1);
                *(__half2*)(out + (size_t)r1g * HID + col) = h;
            }
        }
    }
}

// ---------------- Aggregation + bias + LayerNorm + ReLU ----------------
__device__ __forceinline__ float block_reduce_64(float v, float* sh) {
    #pragma unroll
    for (int o = 16; o; o >>= 1) v += __shfl_xor_sync(0xffffffffu, v, o);
    int w = threadIdx.x >> 5;
    if ((threadIdx.x & 31) == 0) sh[w] = v;
    __syncthreads();
    float r = sh[0] + sh[1];
    __syncthreads();
    return r;
}

__global__ __launch_bounds__(64)
void k_agg_ln(const __half2* __restrict__ ht2, const int* __restrict__ adj,
              const int* __restrict__ off, const int* __restrict__ deg,
              const float* __restrict__ dinv,
              const float* __restrict__ bias, const float* __restrict__ gamma,
              const float* __restrict__ beta, float* __restrict__ out, int n) {
    __shared__ float sh[2];
    int i = blockIdx.x;
    if (i >= n) return;
    int c = threadIdx.x;

    float2 a = __half22float2(__ldg(&ht2[(size_t)i * 64 + c]));
    int s = __ldg(&off[i]);
    int e = s + __ldg(&deg[i]);     // order-free partition: end = start + degree
    int p = s;
    for (; p + 4 <= e; p += 4) {
        int j0 = __ldg(&adj[p]);
        int j1 = __ldg(&adj[p + 1]);
        int j2 = __ldg(&adj[p + 2]);
        int j3 = __ldg(&adj[p + 3]);
        float2 v0 = __half22float2(__ldg(&ht2[(size_t)j0 * 64 + c]));
        float2 v1 = __half22float2(__ldg(&ht2[(size_t)j1 * 64 + c]));
        float2 v2 = __half22float2(__ldg(&ht2[(size_t)j2 * 64 + c]));
        float2 v3 = __half22float2(__ldg(&ht2[(size_t)j3 * 64 + c]));
        a.x += (v0.x + v1.x) + (v2.x + v3.x);
        a.y += (v0.y + v1.y) + (v2.y + v3.y);
    }
    for (; p < e; ++p) {
        float2 v = __half22float2(__ldg(&ht2[(size_t)__ldg(&adj[p]) * 64 + c]));
        a.x += v.x; a.y += v.y;
    }

    float di = dinv[i];
    float2 bb = ((const float2*)bias)[c];
    float vx = a.x * di + bb.x;
    float vy = a.y * di + bb.y;

    float mu = block_reduce_64(vx + vy, sh) * (1.0f / 128.0f);
    float dx = vx - mu, dy = vy - mu;
    float var = block_reduce_64(dx * dx + dy * dy, sh) * (1.0f / 128.0f);
    float rs = rsqrtf(var + 1e-5f);
    float2 gg = ((const float2*)gamma)[c];
    float2 be = ((const float2*)beta)[c];
    float2 o = make_float2(fmaxf(dx * rs * gg.x + be.x, 0.0f),
                           fmaxf(dy * rs * gg.y + be.y, 0.0f));
    ((float2*)out)[(size_t)i * 64 + c] = o;
}

// ---------------- launch ----------------
extern "C" void kernel_launch(void* const* d_in, const int* in_sizes, int n_in,
                              void* d_out, int out_size) {
    const float* x     = (const float*)d_in[0];
    const int*   edges = (const int*)d_in[1];
    const float* W1    = (const float*)d_in[2];
    const float* b1    = (const float*)d_in[3];
    const float* g1    = (const float*)d_in[4];
    const float* be1   = (const float*)d_in[5];
    const float* W2    = (const float*)d_in[6];
    const float* b2    = (const float*)d_in[7];
    const float* g2    = (const float*)d_in[8];
    const float* be2   = (const float*)d_in[9];
    float* out = (float*)d_out;

    int n = in_sizes[0] / HID;
    int E = in_sizes[1] / 2;
    const int* src = edges;
    const int* dst = edges + E;

    int *deg, *off, *cursor, *adj, *base;
    float *dinv, *act;
    __half* ht;
    unsigned short *whi1, *wlo1, *whi2, *wlo2;
    cudaGetSymbolAddress((void**)&deg, g_deg);
    cudaGetSymbolAddress((void**)&off, g_off);
    cudaGetSymbolAddress((void**)&cursor, g_cursor);
    cudaGetSymbolAddress((void**)&adj, g_adj);
    cudaGetSymbolAddress((void**)&base, g_base);
    cudaGetSymbolAddress((void**)&dinv, g_dinv);
    cudaGetSymbolAddress((void**)&ht, g_ht);
    cudaGetSymbolAddress((void**)&act, g_act);
    cudaGetSymbolAddress((void**)&whi1, g_Whi1);
    cudaGetSymbolAddress((void**)&wlo1, g_Wlo1);
    cudaGetSymbolAddress((void**)&whi2, g_Whi2);
    cudaGetSymbolAddress((void**)&wlo2, g_Wlo2);

    static bool attr_done = false;
    if (!attr_done) {
        cudaFuncSetAttribute(k_gemm_mma, cudaFuncAttributeMaxDynamicSharedMemorySize, GEMM_SMEM);
        attr_done = true;
    }

    int nbN = (n + 255) / 256;
    int nbE = (E + 255) / 256;
    int nbG = (n + 127) / 128;

    // W prep (one launch, both layers)
    k_prepW2<<<128, 256>>>(W1, whi1, wlo1, W2, whi2, wlo2);

    // CSR: count + fused assign
    cudaMemsetAsync(deg, 0, n * sizeof(int));
    cudaMemsetAsync(base, 0, sizeof(int));
    k_count<<<nbE, 256>>>(dst, deg, E);
    k_assign<<<nbN, 256>>>(deg, off, cursor, dinv, base, n);

    // fork: fill_adj (side) || GEMM1 (main)
    bool fork = (g_s2 && g_ev0 && g_ev1);
    if (fork) {
        cudaEventRecord(g_ev0, 0);
        cudaStreamWaitEvent(g_s2, g_ev0, 0);
        k_fill_adj<<<nbE, 256, 0, g_s2>>>(src, dst, cursor, adj, E);
        k_gemm_mma<<<nbG, 256, GEMM_SMEM>>>(x, whi1, wlo1, dinv, ht, n);
        cudaEventRecord(g_ev1, g_s2);
        cudaStreamWaitEvent((cudaStream_t)0, g_ev1, 0);
    } else {
        k_fill_adj<<<nbE, 256>>>(src, dst, cursor, adj, E);
        k_gemm_mma<<<nbG, 256, GEMM_SMEM>>>(x, whi1, wlo1, dinv, ht, n);
    }

    // layer 1 agg + layer 2
    k_agg_ln<<<n, 64>>>((const __half2*)ht, adj, off, deg, dinv, b1, g1, be1, act, n);
    k_gemm_mma<<<nbG, 256, GEMM_SMEM>>>(act, whi2, wlo2, dinv, ht, n);
    k_agg_ln<<<n, 64>>>((const __half2*)ht, adj, off, deg, dinv, b2, g2, be2, out, n);
}

// round 10
// speedup vs baseline: 1.0432x; 1.0432x over previous
#include <cuda_runtime.h>
#include <cuda_bf16.h>
#include <cuda_fp16.h>
#include <cstdint>

#define NN_MAX 50000
#define NE_MAX 800000
#define HID 128

// ---------------- scratch (device globals) ----------------
__device__ int    g_deg[NN_MAX];
__device__ int    g_off[NN_MAX + 1];
__device__ int    g_cursor[NN_MAX];
__device__ int    g_adj[NE_MAX];
__device__ float  g_dinv[NN_MAX];
__device__ __half g_ht[NN_MAX * HID];
__device__ float  g_act[NN_MAX * HID];
__device__ int    g_base[1];
// W hi/lo bf16, [K][N] row-major
__device__ unsigned short g_Whi1[HID * HID];
__device__ unsigned short g_Wlo1[HID * HID];
__device__ unsigned short g_Whi2[HID * HID];
__device__ unsigned short g_Wlo2[HID * HID];

// side stream + events (created at load; no device memory)
static cudaStream_t g_s2 = nullptr;
static cudaEvent_t  g_ev0 = nullptr, g_ev1 = nullptr;
namespace {
struct SideInit {
    SideInit() {
        cudaStreamCreateWithFlags(&g_s2, cudaStreamNonBlocking);
        cudaEventCreateWithFlags(&g_ev0, cudaEventDisableTiming);
        cudaEventCreateWithFlags(&g_ev1, cudaEventDisableTiming);
    }
};
SideInit g_side_init;
}

// ---------------- setup: W prep (both layers) + deg/base zeroing, ONE kernel ----------------
__global__ void k_setup(const float* __restrict__ Wa, unsigned short* hia, unsigned short* loa,
                        const float* __restrict__ Wb, unsigned short* hib, unsigned short* lob,
                        int* deg, int* base, int n) {
    int t = blockIdx.x * 256 + threadIdx.x;   // 256 blocks x 256 = 65536 threads
    if (t < HID * HID) {
        float w = Wa[t];
        __nv_bfloat16 h = __float2bfloat16(w);
        float r = w - __bfloat162float(h);
        hia[t] = __bfloat16_as_ushort(h);
        loa[t] = __bfloat16_as_ushort(__float2bfloat16(r));
    } else if (t < 2 * HID * HID) {
        int i = t - HID * HID;
        float w = Wb[i];
        __nv_bfloat16 h = __float2bfloat16(w);
        float r = w - __bfloat162float(h);
        hib[i] = __bfloat16_as_ushort(h);
        lob[i] = __bfloat16_as_ushort(__float2bfloat16(r));
    }
    if (t < n) deg[t] = 0;
    if (t == 0) *base = 0;
}

// ---------------- CSR build ----------------
__global__ void k_count(const int* __restrict__ dst, int* deg, int E) {
    int e = blockIdx.x * blockDim.x + threadIdx.x;
    if (e < E) atomicAdd(&deg[dst[e]], 1);
}

// fused: block-local exclusive scan + atomic block base.
// off[] is an ORDER-FREE partition (not monotonic); end = off[i] + deg[i].
__global__ void k_assign(const int* __restrict__ deg, int* off, int* cursor,
                         float* dinv, int* base, int n) {
    __shared__ int s[256];
    __shared__ int blk_base;
    int tid = threadIdx.x;
    int gid = blockIdx.x * 256 + tid;
    int v = (gid < n) ? deg[gid] : 0;
    s[tid] = v;
    __syncthreads();
    #pragma unroll
    for (int d = 1; d < 256; d <<= 1) {
        int t = (tid >= d) ? s[tid - d] : 0;
        __syncthreads();
        s[tid] += t;
        __syncthreads();
    }
    if (tid == 255) blk_base = atomicAdd(base, s[255]);
    __syncthreads();
    if (gid < n) {
        int o = blk_base + s[tid] - v;
        off[gid] = o;
        cursor[gid] = o;
        dinv[gid] = rsqrtf((float)(v + 1));
    }
}

__global__ void k_fill_adj(const int* __restrict__ src, const int* __restrict__ dst,
                           int* cursor, int* adj, int E) {
    int e = blockIdx.x * blockDim.x + threadIdx.x;
    if (e < E) {
        int d = dst[e];
        int pos = atomicAdd(&cursor[d], 1);
        adj[pos] = src[e];
    }
}

// ---------------- HMMA GEMM: ht[i,:] = fp16( (X[i,:] @ W) * dinv[i] ) ----------------
#define LDA 136
#define TILE_B (128 * LDA * 2)
#define GEMM_SMEM (4 * TILE_B)

__device__ __forceinline__ uint32_t smem_u32(const void* p) {
    uint32_t a;
    asm("{ .reg .u64 t; cvta.to.shared.u64 t, %1; cvt.u32.u64 %0, t; }" : "=r"(a) : "l"(p));
    return a;
}
__device__ __forceinline__ void ldsm_x4(uint32_t* r, uint32_t addr) {
    asm volatile("ldmatrix.sync.aligned.m8n8.x4.shared.b16 {%0,%1,%2,%3}, [%4];"
                 : "=r"(r[0]), "=r"(r[1]), "=r"(r[2]), "=r"(r[3]) : "r"(addr));
}
__device__ __forceinline__ void ldsm_x4t(uint32_t* r, uint32_t addr) {
    asm volatile("ldmatrix.sync.aligned.m8n8.x4.trans.shared.b16 {%0,%1,%2,%3}, [%4];"
                 : "=r"(r[0]), "=r"(r[1]), "=r"(r[2]), "=r"(r[3]) : "r"(addr));
}
__device__ __forceinline__ void mma_bf16(float* c, const uint32_t* a, const uint32_t* b) {
    asm volatile("mma.sync.aligned.m16n8k16.row.col.f32.bf16.bf16.f32 "
                 "{%0,%1,%2,%3}, {%4,%5,%6,%7}, {%8,%9}, {%0,%1,%2,%3};"
                 : "+f"(c[0]), "+f"(c[1]), "+f"(c[2]), "+f"(c[3])
                 : "r"(a[0]), "r"(a[1]), "r"(a[2]), "r"(a[3]), "r"(b[0]), "r"(b[1]));
}

__global__ __launch_bounds__(256, 1)
void k_gemm_mma(const float* __restrict__ X,
                const unsigned short* __restrict__ Whi,
                const unsigned short* __restrict__ Wlo,
                const float* __restrict__ dinv,
                __half* __restrict__ out, int n)
{
    extern __shared__ char sm[];
    char* pAhi = sm;
    char* pAlo = sm + TILE_B;
    char* pBhi = sm + 2 * TILE_B;
    char* pBlo = sm + 3 * TILE_B;
    uint32_t uAhi = smem_u32(pAhi), uAlo = smem_u32(pAlo);
    uint32_t uBhi = smem_u32(pBhi), uBlo = smem_u32(pBlo);

    int tid = threadIdx.x, wid = tid >> 5, lid = tid & 31;
    int row0 = blockIdx.x * 128;

    // copy W hi/lo into smem (padded rows)
    {
        const uint4* sh = (const uint4*)Whi;
        const uint4* sl = (const uint4*)Wlo;
        uint4* dh = (uint4*)pBhi;
        uint4* dl = (uint4*)pBlo;
        #pragma unroll
        for (int i = 0; i < 8; ++i) {
            int idx = i * 256 + tid;
            int k = idx >> 4, g = idx & 15;
            dh[k * 17 + g] = sh[idx];
            dl[k * 17 + g] = sl[idx];
        }
    }

    // convert X tile fp32 -> bf16 hi/lo
    {
        const float4* Xg = (const float4*)X;
        #pragma unroll
        for (int i = 0; i < 8; ++i) {
            int idx = i * 256 + tid;
            int r = idx >> 4, g = idx & 15;
            int grow = row0 + r;
            float4 v0 = make_float4(0.f, 0.f, 0.f, 0.f);
            float4 v1 = make_float4(0.f, 0.f, 0.f, 0.f);
            if (grow < n) {
                v0 = __ldg(&Xg[grow * 32 + g * 2]);
                v1 = __ldg(&Xg[grow * 32 + g * 2 + 1]);
            }
            float f[8] = {v0.x, v0.y, v0.z, v0.w, v1.x, v1.y, v1.z, v1.w};
            uint32_t ph[4], pl[4];
            #pragma unroll
            for (int q = 0; q < 4; ++q) {
                __nv_bfloat16 h0 = __float2bfloat16(f[q * 2]);
                __nv_bfloat16 h1 = __float2bfloat16(f[q * 2 + 1]);
                float r0 = f[q * 2]     - __bfloat162float(h0);
                float r1 = f[q * 2 + 1] - __bfloat162float(h1);
                __nv_bfloat16 l0 = __float2bfloat16(r0);
                __nv_bfloat16 l1 = __float2bfloat16(r1);
                ph[q] = ((uint32_t)__bfloat16_as_ushort(h1) << 16) | __bfloat16_as_ushort(h0);
                pl[q] = ((uint32_t)__bfloat16_as_ushort(l1) << 16) | __bfloat16_as_ushort(l0);
            }
            uint4* dh = (uint4*)pAhi;
            uint4* dl = (uint4*)pAlo;
            dh[r * 17 + g] = make_uint4(ph[0], ph[1], ph[2], ph[3]);
            dl[r * 17 + g] = make_uint4(pl[0], pl[1], pl[2], pl[3]);
        }
    }
    __syncthreads();

    // mainloop — x4t B loads (2 col-tiles per LDSM)
    int m0 = wid * 16;
    float c[16][4];
    #pragma unroll
    for (int t = 0; t < 16; ++t)
        #pragma unroll
        for (int q = 0; q < 4; ++q) c[t][q] = 0.f;

    int a_row = m0 + (lid & 15);
    int a_k8  = (lid >> 4) * 8;
    int b_row = (lid & 15);        // rows kb+0..15 within k-step
    int b_c8  = (lid >> 4) * 8;    // lanes 16-31 take the second 8-col tile

    #pragma unroll
    for (int ks = 0; ks < 8; ++ks) {
        int kb = ks * 16;
        uint32_t ahi[4], alo[4];
        uint32_t a_off = ((uint32_t)(a_row * LDA + kb + a_k8)) * 2u;
        ldsm_x4(ahi, uAhi + a_off);
        ldsm_x4(alo, uAlo + a_off);

        uint32_t b_base = ((uint32_t)((kb + b_row) * LDA)) * 2u;
        #pragma unroll
        for (int ntp = 0; ntp < 8; ++ntp) {
            uint32_t bhi[4], blo[4];
            uint32_t b_off = b_base + (uint32_t)(ntp * 16 + b_c8) * 2u;
            ldsm_x4t(bhi, uBhi + b_off);
            ldsm_x4t(blo, uBlo + b_off);
            mma_bf16(c[ntp * 2],     ahi, bhi);
            mma_bf16(c[ntp * 2],     ahi, blo);
            mma_bf16(c[ntp * 2],     alo, bhi);
            mma_bf16(c[ntp * 2 + 1], ahi, bhi + 2);
            mma_bf16(c[ntp * 2 + 1], ahi, blo + 2);
            mma_bf16(c[ntp * 2 + 1], alo, bhi + 2);
        }
    }

    // epilogue: scale by dinv, store fp16
    {
        int ml = lid >> 2;
        int n0 = (lid & 3) * 2;
        int r0g = row0 + m0 + ml;
        int r1g = r0g + 8;
        float s0 = (r0g < n) ? dinv[r0g] : 0.f;
        float s1 = (r1g < n) ? dinv[r1g] : 0.f;
        #pragma unroll
        for (int nt = 0; nt < 16; ++nt) {
            int col = nt * 8 + n0;
            if (r0g < n) {
                __half2 h = __floats2half2_rn(c[nt][0] * s0, c[nt][1] * s0);
                *(__half2*)(out + (size_t)r0g * HID + col) = h;
            }
            if (r1g < n) {
                __half2 h = __floats2half2_rn(c[nt][2] * s1, c[nt][3] * s1);
                *(__half2*)(out + (size_t)r1g * HID + col) = h;
            }
        }
    }
}

// ---------------- Aggregation + bias + LayerNorm + ReLU ----------------
__device__ __forceinline__ float block_reduce_64(float v, float* sh) {
    #pragma unroll
    for (int o = 16; o; o >>= 1) v += __shfl_xor_sync(0xffffffffu, v, o);
    int w = threadIdx.x >> 5;
    if ((threadIdx.x & 31) == 0) sh[w] = v;
    __syncthreads();
    float r = sh[0] + sh[1];
    __syncthreads();
    return r;
}

__global__ __launch_bounds__(64)
void k_agg_ln(const __half2* __restrict__ ht2, const int* __restrict__ adj,
              const int* __restrict__ off, const int* __restrict__ deg,
              const float* __restrict__ dinv,
              const float* __restrict__ bias, const float* __restrict__ gamma,
              const float* __restrict__ beta, float* __restrict__ out, int n) {
    __shared__ float sh[2];
    int i = blockIdx.x;
    if (i >= n) return;
    int c = threadIdx.x;

    float2 a = __half22float2(__ldg(&ht2[(size_t)i * 64 + c]));
    int s = __ldg(&off[i]);
    int e = s + __ldg(&deg[i]);     // order-free partition: end = start + degree
    int p = s;
    for (; p + 4 <= e; p += 4) {
        int j0 = __ldg(&adj[p]);
        int j1 = __ldg(&adj[p + 1]);
        int j2 = __ldg(&adj[p + 2]);
        int j3 = __ldg(&adj[p + 3]);
        float2 v0 = __half22float2(__ldg(&ht2[(size_t)j0 * 64 + c]));
        float2 v1 = __half22float2(__ldg(&ht2[(size_t)j1 * 64 + c]));
        float2 v2 = __half22float2(__ldg(&ht2[(size_t)j2 * 64 + c]));
        float2 v3 = __half22float2(__ldg(&ht2[(size_t)j3 * 64 + c]));
        a.x += (v0.x + v1.x) + (v2.x + v3.x);
        a.y += (v0.y + v1.y) + (v2.y + v3.y);
    }
    for (; p < e; ++p) {
        float2 v = __half22float2(__ldg(&ht2[(size_t)__ldg(&adj[p]) * 64 + c]));
        a.x += v.x; a.y += v.y;
    }

    float di = dinv[i];
    float2 bb = ((const float2*)bias)[c];
    float vx = a.x * di + bb.x;
    float vy = a.y * di + bb.y;

    float mu = block_reduce_64(vx + vy, sh) * (1.0f / 128.0f);
    float dx = vx - mu, dy = vy - mu;
    float var = block_reduce_64(dx * dx + dy * dy, sh) * (1.0f / 128.0f);
    float rs = rsqrtf(var + 1e-5f);
    float2 gg = ((const float2*)gamma)[c];
    float2 be = ((const float2*)beta)[c];
    float2 o = make_float2(fmaxf(dx * rs * gg.x + be.x, 0.0f),
                           fmaxf(dy * rs * gg.y + be.y, 0.0f));
    ((float2*)out)[(size_t)i * 64 + c] = o;
}

// ---------------- launch ----------------
extern "C" void kernel_launch(void* const* d_in, const int* in_sizes, int n_in,
                              void* d_out, int out_size) {
    const float* x     = (const float*)d_in[0];
    const int*   edges = (const int*)d_in[1];
    const float* W1    = (const float*)d_in[2];
    const float* b1    = (const float*)d_in[3];
    const float* g1    = (const float*)d_in[4];
    const float* be1   = (const float*)d_in[5];
    const float* W2    = (const float*)d_in[6];
    const float* b2    = (const float*)d_in[7];
    const float* g2    = (const float*)d_in[8];
    const float* be2   = (const float*)d_in[9];
    float* out = (float*)d_out;

    int n = in_sizes[0] / HID;
    int E = in_sizes[1] / 2;
    const int* src = edges;
    const int* dst = edges + E;

    int *deg, *off, *cursor, *adj, *base;
    float *dinv, *act;
    __half* ht;
    unsigned short *whi1, *wlo1, *whi2, *wlo2;
    cudaGetSymbolAddress((void**)&deg, g_deg);
    cudaGetSymbolAddress((void**)&off, g_off);
    cudaGetSymbolAddress((void**)&cursor, g_cursor);
    cudaGetSymbolAddress((void**)&adj, g_adj);
    cudaGetSymbolAddress((void**)&base, g_base);
    cudaGetSymbolAddress((void**)&dinv, g_dinv);
    cudaGetSymbolAddress((void**)&ht, g_ht);
    cudaGetSymbolAddress((void**)&act, g_act);
    cudaGetSymbolAddress((void**)&whi1, g_Whi1);
    cudaGetSymbolAddress((void**)&wlo1, g_Wlo1);
    cudaGetSymbolAddress((void**)&whi2, g_Whi2);
    cudaGetSymbolAddress((void**)&wlo2, g_Wlo2);

    static bool attr_done = false;
    if (!attr_done) {
        cudaFuncSetAttribute(k_gemm_mma, cudaFuncAttributeMaxDynamicSharedMemorySize, GEMM_SMEM);
        attr_done = true;
    }

    int nbN = (n + 255) / 256;
    int nbE = (E + 255) / 256;
    int nbG = (n + 127) / 128;

    // setup: W prep + deg/base zeroing (one kernel)
    k_setup<<<256, 256>>>(W1, whi1, wlo1, W2, whi2, wlo2, deg, base, n);

    // CSR: count + fused assign
    k_count<<<nbE, 256>>>(dst, deg, E);
    k_assign<<<nbN, 256>>>(deg, off, cursor, dinv, base, n);

    // fork: fill_adj (side) || GEMM1 (main)
    bool fork = (g_s2 && g_ev0 && g_ev1);
    if (fork) {
        cudaEventRecord(g_ev0, 0);
        cudaStreamWaitEvent(g_s2, g_ev0, 0);
        k_fill_adj<<<nbE, 256, 0, g_s2>>>(src, dst, cursor, adj, E);
        k_gemm_mma<<<nbG, 256, GEMM_SMEM>>>(x, whi1, wlo1, dinv, ht, n);
        cudaEventRecord(g_ev1, g_s2);
        cudaStreamWaitEvent((cudaStream_t)0, g_ev1, 0);
    } else {
        k_fill_adj<<<nbE, 256>>>(src, dst, cursor, adj, E);
        k_gemm_mma<<<nbG, 256, GEMM_SMEM>>>(x, whi1, wlo1, dinv, ht, n);
    }

    // layer 1 agg + layer 2
    k_agg_ln<<<n, 64>>>((const __half2*)ht, adj, off, deg, dinv, b1, g1, be1, act, n);
    k_gemm_mma<<<nbG, 256, GEMM_SMEM>>>(act, whi2, wlo2, dinv, ht, n);
    k_agg_ln<<<n, 64>>>((const __half2*)ht, adj, off, deg, dinv, b2, g2, be2, out, n);
}